// round 2
// baseline (speedup 1.0000x reference)
#include <cuda_runtime.h>
#include <cuda_bf16.h>
#include <math.h>

// ---------------------------------------------------------------------------
// Problem constants
// ---------------------------------------------------------------------------
#define D_MODEL 1024
#define NHEAD   8
#define HDIM    128          // D/NHEAD
#define NQ      256
#define BATCH   8
#define SEQ_S   4096         // HM*WM
#define FF_DIM  4096
#define M_TOK   (NQ*BATCH)       // 2048
#define M_MEM   (SEQ_S*BATCH)    // 32768

// ---------------------------------------------------------------------------
// Scratch: one big __device__ array (no runtime allocation allowed)
// all offsets in floats
// ---------------------------------------------------------------------------
#define OFF_X      0LL
#define OFF_QKV    (OFF_X    + 2097152LL)   // 2048*3072
#define OFF_PACK   (OFF_QKV  + 6291456LL)   // q,k,v packed [64,256,128] each
#define OFF_SCORES (OFF_PACK + 6291456LL)   // max(64*256*256, 8*256*4096)
#define OFF_O      (OFF_SCORES + 8388608LL) // 64*256*128 == 8*256*1024
#define OFF_OREP   (OFF_O    + 2097152LL)
#define OFF_Q1     (OFF_OREP + 2097152LL)
#define OFF_QC     (OFF_Q1   + 2097152LL)   // cross-attn Q [8,256,1024]
#define OFF_K      (OFF_QC   + 2097152LL)   // [8,4096,1024]
#define OFF_V      (OFF_K    + 33554432LL)
#define OFF_Q2     (OFF_V    + 33554432LL)
#define OFF_H      (OFF_Q2   + 2097152LL)   // FFN hidden [2048,4096]
#define OFF_QM     (OFF_H    + 8388608LL)   // query gathered to [B,NQ,D]
#define SCRATCH_TOTAL (OFF_QM + 2097152LL)  // = 111,149,056 floats (~445 MB)

__device__ float g_scratch[SCRATCH_TOTAL];

// ---------------------------------------------------------------------------
// Generic batched GEMM:  C = act( alpha * A @ op(B) + bias + resid )
//   A: row-major [M,K], per-batch stride bA, leading dim lda
//   B: BLAYOUT==0 -> B is [N,K] row-major (compute A @ B^T), ld = ldb
//      BLAYOUT==1 -> B is [K,N] row-major (compute A @ B),   ld = ldb
//   C row remap: permP>0 -> out_row = (m % permP)*permQ + m/permP else m
//   C element index = z*bC + out_row*N + n  (resid uses same index)
//   ACT: 0 none, 1 exact gelu, 2 sigmoid
// Tile: 128x128x8, 256 threads, 8x8 per thread. All dims must be multiples
// of tile (they are for every call in this problem).
// ---------------------------------------------------------------------------
__device__ __forceinline__ float gelu_exact(float x) {
    return 0.5f * x * (1.0f + erff(x * 0.70710678118654752f));
}

template<int BLAYOUT, int ACT>
__global__ void __launch_bounds__(256)
gemm_k(const float* __restrict__ A, const float* __restrict__ B,
       const float* __restrict__ bias, const float* __restrict__ resid,
       float* __restrict__ C,
       int M, int N, int K, int lda, int ldb,
       long long bA, long long bB, long long bC,
       float alpha, int permP, int permQ)
{
    const int z  = blockIdx.z;
    const float* Ab = A + (long long)z * bA;
    const float* Bb = B + (long long)z * bB;
    const int m0 = blockIdx.y * 128;
    const int n0 = blockIdx.x * 128;

    __shared__ float As[8][128];
    __shared__ float Bs[8][128];

    const int tid = threadIdx.x;
    const int ar  = tid >> 1;            // 0..127
    const int ac  = (tid & 1) * 4;       // 0 or 4
    const int bkr = tid >> 5;            // 0..7   (BN layout)
    const int bnc = (tid & 31) * 4;      // 0..124 (BN layout)

    const float* Aptr = Ab + (long long)(m0 + ar) * lda + ac;
    const float* Bptr;
    if (BLAYOUT == 0) Bptr = Bb + (long long)(n0 + ar) * ldb + ac;
    else              Bptr = Bb + (long long)bkr * ldb + n0 + bnc;

    float acc[8][8];
    #pragma unroll
    for (int i = 0; i < 8; i++)
        #pragma unroll
        for (int j = 0; j < 8; j++) acc[i][j] = 0.f;

    const int ty = tid >> 4, tx = tid & 15;
    const int ry = ty * 8, cx = tx * 8;
    const int nk = K >> 3;

    // tile 0
    {
        float4 a0 = *(const float4*)Aptr;
        As[ac+0][ar] = a0.x; As[ac+1][ar] = a0.y;
        As[ac+2][ar] = a0.z; As[ac+3][ar] = a0.w;
        if (BLAYOUT == 0) {
            float4 b0 = *(const float4*)Bptr;
            Bs[ac+0][ar] = b0.x; Bs[ac+1][ar] = b0.y;
            Bs[ac+2][ar] = b0.z; Bs[ac+3][ar] = b0.w;
        } else {
            *(float4*)(&Bs[bkr][bnc]) = *(const float4*)Bptr;
        }
    }
    __syncthreads();

    float4 av, bv;
    for (int kt = 0; kt < nk; kt++) {
        const bool more = (kt + 1 < nk);
        if (more) {
            av = *(const float4*)(Aptr + (long long)(kt + 1) * 8);
            if (BLAYOUT == 0) bv = *(const float4*)(Bptr + (long long)(kt + 1) * 8);
            else              bv = *(const float4*)(Bptr + (long long)(kt + 1) * 8 * ldb);
        }
        #pragma unroll
        for (int k = 0; k < 8; k++) {
            float4 a0 = *(const float4*)(&As[k][ry]);
            float4 a1 = *(const float4*)(&As[k][ry + 4]);
            float4 b0 = *(const float4*)(&Bs[k][cx]);
            float4 b1 = *(const float4*)(&Bs[k][cx + 4]);
            float a[8] = {a0.x, a0.y, a0.z, a0.w, a1.x, a1.y, a1.z, a1.w};
            float b[8] = {b0.x, b0.y, b0.z, b0.w, b1.x, b1.y, b1.z, b1.w};
            #pragma unroll
            for (int i = 0; i < 8; i++)
                #pragma unroll
                for (int j = 0; j < 8; j++)
                    acc[i][j] = fmaf(a[i], b[j], acc[i][j]);
        }
        __syncthreads();
        if (more) {
            As[ac+0][ar] = av.x; As[ac+1][ar] = av.y;
            As[ac+2][ar] = av.z; As[ac+3][ar] = av.w;
            if (BLAYOUT == 0) {
                Bs[ac+0][ar] = bv.x; Bs[ac+1][ar] = bv.y;
                Bs[ac+2][ar] = bv.z; Bs[ac+3][ar] = bv.w;
            } else {
                *(float4*)(&Bs[bkr][bnc]) = bv;
            }
            __syncthreads();
        }
    }

    // epilogue
    #pragma unroll
    for (int i = 0; i < 8; i++) {
        const int gm = m0 + ry + i;
        const int rm = (permP > 0) ? ((gm % permP) * permQ + gm / permP) : gm;
        const long long base = (long long)z * bC + (long long)rm * N;
        #pragma unroll
        for (int j = 0; j < 8; j++) {
            const int gn = n0 + cx + j;
            float v = acc[i][j] * alpha;
            if (bias)  v += bias[gn];
            if (resid) v += resid[base + gn];
            if (ACT == 1) v = gelu_exact(v);
            else if (ACT == 2) v = 1.0f / (1.0f + expf(-v));
            C[base + gn] = v;
        }
    }
}

// ---------------------------------------------------------------------------
// LayerNorm over D=1024, one block per row, 256 threads, 4 elems/thread
// ---------------------------------------------------------------------------
__global__ void ln_k(const float* __restrict__ x, const float* __restrict__ g,
                     const float* __restrict__ b, float* __restrict__ y)
{
    const long long row = blockIdx.x;
    const float* xr = x + row * D_MODEL;
    float* yr = y + row * D_MODEL;
    const int t = threadIdx.x;

    float v[4], s = 0.f, s2 = 0.f;
    #pragma unroll
    for (int i = 0; i < 4; i++) {
        v[i] = xr[t + i * 256];
        s  += v[i];
        s2 += v[i] * v[i];
    }
    // warp reduce
    #pragma unroll
    for (int o = 16; o > 0; o >>= 1) {
        s  += __shfl_xor_sync(0xFFFFFFFFu, s,  o);
        s2 += __shfl_xor_sync(0xFFFFFFFFu, s2, o);
    }
    __shared__ float shs[8], shs2[8];
    if ((t & 31) == 0) { shs[t >> 5] = s; shs2[t >> 5] = s2; }
    __syncthreads();
    float S = 0.f, S2 = 0.f;
    #pragma unroll
    for (int w = 0; w < 8; w++) { S += shs[w]; S2 += shs2[w]; }

    const float mean = S * (1.0f / D_MODEL);
    const float var  = S2 * (1.0f / D_MODEL) - mean * mean;
    const float inv  = rsqrtf(var + 1e-5f);
    #pragma unroll
    for (int i = 0; i < 4; i++) {
        const int c = t + i * 256;
        yr[c] = (v[i] - mean) * inv * g[c] + b[c];
    }
}

// ---------------------------------------------------------------------------
// Row softmax. One block per row, 256 threads, cols/256 elems per thread.
// If pm != nullptr, adds log(pm + 1e-6) first (same [row,col] layout).
// ---------------------------------------------------------------------------
__global__ void softmax_k(float* __restrict__ s, const float* __restrict__ pm,
                          int cols)
{
    const long long row = blockIdx.x;
    float* r = s + row * cols;
    const float* pmr = pm ? pm + row * cols : nullptr;
    const int t = threadIdx.x;
    const int nc = cols >> 8;   // 1 or 16

    float lv[16];
    float mx = -1e30f;
    for (int i = 0; i < nc; i++) {
        float v = r[t + (i << 8)];
        if (pmr) v += logf(pmr[t + (i << 8)] + 1e-6f);
        lv[i] = v;
        mx = fmaxf(mx, v);
    }
    #pragma unroll
    for (int o = 16; o > 0; o >>= 1)
        mx = fmaxf(mx, __shfl_xor_sync(0xFFFFFFFFu, mx, o));
    __shared__ float shm[8], shsum[8];
    if ((t & 31) == 0) shm[t >> 5] = mx;
    __syncthreads();
    float MX = shm[0];
    #pragma unroll
    for (int w = 1; w < 8; w++) MX = fmaxf(MX, shm[w]);

    float sum = 0.f;
    for (int i = 0; i < nc; i++) {
        const float e = expf(lv[i] - MX);
        lv[i] = e;
        sum += e;
    }
    #pragma unroll
    for (int o = 16; o > 0; o >>= 1)
        sum += __shfl_xor_sync(0xFFFFFFFFu, sum, o);
    if ((t & 31) == 0) shsum[t >> 5] = sum;
    __syncthreads();
    float SUM = 0.f;
    #pragma unroll
    for (int w = 0; w < 8; w++) SUM += shsum[w];

    const float inv = 1.0f / SUM;
    for (int i = 0; i < nc; i++) r[t + (i << 8)] = lv[i] * inv;
}

// ---------------------------------------------------------------------------
// Repack kernels
// ---------------------------------------------------------------------------
// qkv [L*B, 3D] rows (l*8+b)  ->  pack[sec][b*8+h][l][d]   (q,k,v contiguous)
__global__ void repack_qkv_k(const float* __restrict__ qkv, float* __restrict__ pack)
{
    const long long gid = (long long)blockIdx.x * 256 + threadIdx.x;  // < 3*64*256*128
    const int d   = gid & 127;
    const int l   = (gid >> 7) & 255;
    const int bh  = (gid >> 15) & 63;
    const int sec = (int)(gid >> 21);
    const int b = bh >> 3, h = bh & 7;
    const long long in = (long long)(l * BATCH + b) * (3 * D_MODEL)
                         + sec * D_MODEL + h * HDIM + d;
    pack[gid] = qkv[in];
}

// o packed [b*8+h][l][d]  ->  [l*8+b][h*128+d]
__global__ void repack_o_k(const float* __restrict__ o, float* __restrict__ out)
{
    const long long gid = (long long)blockIdx.x * 256 + threadIdx.x;  // < 2048*1024
    const int c = gid & 1023;
    const int m = (int)(gid >> 10);
    const int l = m >> 3, b = m & 7;
    const int h = c >> 7, d = c & 127;
    out[gid] = o[((long long)(b * 8 + h) * 256 + l) * 128 + d];
}

// final query [q*8+b][d]  ->  [b*256+q][d]
__global__ void repack_qmask_k(const float* __restrict__ q, float* __restrict__ out)
{
    const long long gid = (long long)blockIdx.x * 256 + threadIdx.x;  // < 2048*1024
    const int d = gid & 1023;
    const int m = (int)(gid >> 10);
    const int b = m >> 8, qq = m & 255;
    out[gid] = q[(long long)(qq * 8 + b) * 1024 + d];
}

// ---------------------------------------------------------------------------
// kernel_launch
// ---------------------------------------------------------------------------
extern "C" void kernel_launch(void* const* d_in, const int* in_sizes, int n_in,
                              void* d_out, int out_size)
{
    const float* query    = (const float*)d_in[0];
    const float* memory   = (const float*)d_in[1];
    const float* prevmask = (const float*)d_in[2];
    // d_in[3], d_in[4] = h_mem, w_mem (ints, constant 64)
    const float* sa_in_w  = (const float*)d_in[5];
    const float* sa_in_b  = (const float*)d_in[6];
    const float* sa_out_w = (const float*)d_in[7];
    const float* sa_out_b = (const float*)d_in[8];
    const float* ln1_g = (const float*)d_in[9];
    const float* ln1_b = (const float*)d_in[10];
    const float* ln2_g = (const float*)d_in[11];
    const float* ln2_b = (const float*)d_in[12];
    const float* ln3_g = (const float*)d_in[13];
    const float* ln3_b = (const float*)d_in[14];
    const float* wq = (const float*)d_in[15];
    const float* bq = (const float*)d_in[16];
    const float* wk = (const float*)d_in[17];
    const float* bk = (const float*)d_in[18];
    const float* wv = (const float*)d_in[19];
    const float* bv = (const float*)d_in[20];
    const float* wo = (const float*)d_in[21];
    const float* bo = (const float*)d_in[22];
    const float* w1 = (const float*)d_in[23];
    const float* b1 = (const float*)d_in[24];
    const float* w2 = (const float*)d_in[25];
    const float* b2 = (const float*)d_in[26];
    const float* mask_w = (const float*)d_in[27];
    const float* mask_b = (const float*)d_in[28];

    float* scr = nullptr;
    cudaGetSymbolAddress((void**)&scr, g_scratch);

    float* gx    = scr + OFF_X;
    float* gqkv  = scr + OFF_QKV;
    float* gq    = scr + OFF_PACK;
    float* gk    = scr + OFF_PACK + 2097152LL;
    float* gv    = scr + OFF_PACK + 4194304LL;
    float* gsc   = scr + OFF_SCORES;
    float* go    = scr + OFF_O;
    float* gorep = scr + OFF_OREP;
    float* gq1   = scr + OFF_Q1;
    float* gQc   = scr + OFF_QC;
    float* gK    = scr + OFF_K;
    float* gV    = scr + OFF_V;
    float* gq2   = scr + OFF_Q2;
    float* gh    = scr + OFF_H;
    float* gqm   = scr + OFF_QM;

    float* out_q = (float*)d_out;                       // [NQ,B,D]
    float* out_m = out_q + (long long)M_TOK * D_MODEL;  // [B,NQ,HM,WM]

    const float inv_sqrt_hd = 0.088388347648318447f;    // 1/sqrt(128)
    const float inv_sqrt_d  = 0.03125f;                 // 1/sqrt(1024)

    // --- 1. ln1(query) ---
    ln_k<<<M_TOK, 256>>>(query, ln1_g, ln1_b, gx);

    // --- 2. QKV projection: [2048,3072] ---
    gemm_k<0,0><<<dim3(24,16,1), 256>>>(gx, sa_in_w, sa_in_b, nullptr, gqkv,
        M_TOK, 3*D_MODEL, D_MODEL, D_MODEL, D_MODEL, 0, 0, 0, 1.0f, 0, 0);

    // --- 3. pack q,k,v -> [B*H,256,128] ---
    repack_qkv_k<<<24576, 256>>>(gqkv, gq);

    // --- 4. self-attn scores (batched 64): [256,256] = q @ k^T * 1/sqrt(hd) ---
    gemm_k<0,0><<<dim3(2,2,64), 256>>>(gq, gk, nullptr, nullptr, gsc,
        NQ, NQ, HDIM, HDIM, HDIM, 256LL*128, 256LL*128, 256LL*256,
        inv_sqrt_hd, 0, 0);

    // --- 5. softmax rows (64*256 rows of 256) ---
    softmax_k<<<64*256, 256>>>(gsc, nullptr, 256);

    // --- 6. o = attn @ v (batched 64): [256,128] ---
    gemm_k<1,0><<<dim3(1,2,64), 256>>>(gsc, gv, nullptr, nullptr, go,
        NQ, HDIM, NQ, NQ, HDIM, 256LL*256, 256LL*128, 256LL*128, 1.0f, 0, 0);

    // --- 7. repack o -> [2048,1024] ---
    repack_o_k<<<8192, 256>>>(go, gorep);

    // --- 8. self out-proj + residual: q1 = query + o @ Wout^T + b ---
    gemm_k<0,0><<<dim3(8,16,1), 256>>>(gorep, sa_out_w, sa_out_b, query, gq1,
        M_TOK, D_MODEL, D_MODEL, D_MODEL, D_MODEL, 0, 0, 0, 1.0f, 0, 0);

    // --- 9. ln2(q1) ---
    ln_k<<<M_TOK, 256>>>(gq1, ln2_g, ln2_b, gx);

    // --- 10. Q = ln2 @ wq^T + bq, scattered to [B,NQ,D] ---
    gemm_k<0,0><<<dim3(8,16,1), 256>>>(gx, wq, bq, nullptr, gQc,
        M_TOK, D_MODEL, D_MODEL, D_MODEL, D_MODEL, 0, 0, 0, 1.0f, 8, 256);

    // --- 11/12. K,V = memory @ w^T + b, scattered to [B,S,D] ---
    gemm_k<0,0><<<dim3(8,256,1), 256>>>(memory, wk, bk, nullptr, gK,
        M_MEM, D_MODEL, D_MODEL, D_MODEL, D_MODEL, 0, 0, 0, 1.0f, 8, 4096);
    gemm_k<0,0><<<dim3(8,256,1), 256>>>(memory, wv, bv, nullptr, gV,
        M_MEM, D_MODEL, D_MODEL, D_MODEL, D_MODEL, 0, 0, 0, 1.0f, 8, 4096);

    // --- 13. cross scores (batched 8): [256,4096] = Q @ K^T / 32 ---
    gemm_k<0,0><<<dim3(32,2,8), 256>>>(gQc, gK, nullptr, nullptr, gsc,
        NQ, SEQ_S, D_MODEL, D_MODEL, D_MODEL,
        256LL*1024, 4096LL*1024, 256LL*4096, inv_sqrt_d, 0, 0);

    // --- 14. softmax + log(prev_mask+1e-6) (2048 rows of 4096) ---
    softmax_k<<<BATCH*NQ, 256>>>(gsc, prevmask, SEQ_S);

    // --- 15. attn_out = attn @ V (batched 8): [256,1024] ---
    gemm_k<1,0><<<dim3(8,2,8), 256>>>(gsc, gV, nullptr, nullptr, go,
        NQ, D_MODEL, SEQ_S, SEQ_S, D_MODEL,
        256LL*4096, 4096LL*1024, 256LL*1024, 1.0f, 0, 0);

    // --- 16. cross out-proj + residual, permuted back to [NQ,B,D] ---
    gemm_k<0,0><<<dim3(8,16,1), 256>>>(go, wo, bo, gq1, gq2,
        M_TOK, D_MODEL, D_MODEL, D_MODEL, D_MODEL, 0, 0, 0, 1.0f, 256, 8);

    // --- 17. ln3(q2) ---
    ln_k<<<M_TOK, 256>>>(gq2, ln3_g, ln3_b, gx);

    // --- 18. FFN1 + GELU: [2048,4096] ---
    gemm_k<0,1><<<dim3(32,16,1), 256>>>(gx, w1, b1, nullptr, gh,
        M_TOK, FF_DIM, D_MODEL, D_MODEL, D_MODEL, 0, 0, 0, 1.0f, 0, 0);

    // --- 19. FFN2 + residual -> final query (to d_out) ---
    gemm_k<0,0><<<dim3(8,16,1), 256>>>(gh, w2, b2, gq2, out_q,
        M_TOK, D_MODEL, FF_DIM, FF_DIM, FF_DIM, 0, 0, 0, 1.0f, 0, 0);

    // --- 20. gather final query to [B,NQ,D] ---
    repack_qmask_k<<<8192, 256>>>(out_q, gqm);

    // --- 21. mask logits + sigmoid -> [B,NQ,4096] ---
    gemm_k<0,2><<<dim3(32,16,1), 256>>>(gqm, mask_w, mask_b, nullptr, out_m,
        M_TOK, SEQ_S, D_MODEL, D_MODEL, D_MODEL, 0, 0, 0, 1.0f, 0, 0);
}

// round 3
// speedup vs baseline: 2.6753x; 2.6753x over previous
#include <cuda_runtime.h>
#include <cuda_bf16.h>
#include <math.h>

// ---------------------------------------------------------------------------
// Problem constants
// ---------------------------------------------------------------------------
#define D_MODEL 1024
#define NHEAD   8
#define HDIM    128
#define NQ      256
#define BATCH   8
#define SEQ_S   4096
#define FF_DIM  4096
#define M_TOK   (NQ*BATCH)       // 2048
#define M_MEM   (SEQ_S*BATCH)    // 32768

// ---------------------------------------------------------------------------
// Scratch
// ---------------------------------------------------------------------------
#define OFF_X      0LL
#define OFF_QKV    (OFF_X    + 2097152LL)
#define OFF_PACK   (OFF_QKV  + 6291456LL)
#define OFF_SCORES (OFF_PACK + 6291456LL)
#define OFF_O      (OFF_SCORES + 8388608LL)
#define OFF_OREP   (OFF_O    + 2097152LL)
#define OFF_Q1     (OFF_OREP + 2097152LL)
#define OFF_QC     (OFF_Q1   + 2097152LL)
#define OFF_K      (OFF_QC   + 2097152LL)
#define OFF_V      (OFF_K    + 33554432LL)
#define OFF_Q2     (OFF_V    + 33554432LL)
#define OFF_H      (OFF_Q2   + 2097152LL)
#define OFF_QM     (OFF_H    + 8388608LL)
#define SCRATCH_TOTAL (OFF_QM + 2097152LL)

__device__ float g_scratch[SCRATCH_TOTAL];

// ---------------------------------------------------------------------------
// Helpers
// ---------------------------------------------------------------------------
__device__ __forceinline__ float gelu_exact(float x) {
    return 0.5f * x * (1.0f + erff(x * 0.70710678118654752f));
}
__device__ __forceinline__ unsigned f2tf(float x) {
    unsigned u;
    asm("cvt.rna.tf32.f32 %0, %1;" : "=r"(u) : "f"(x));
    return u;
}
__device__ __forceinline__ float f2tf_f(float x) {
    return __uint_as_float(f2tf(x));
}

// ---------------------------------------------------------------------------
// Tensor-core batched GEMM (tf32 mma.sync, fp32 accumulate)
//   C = act( alpha * A @ op(B) + bias + resid )
//   A row-major [M,K]. BLAYOUT==0: B is [N,K] (A@B^T). BLAYOUT==1: B is [K,N].
//   Row remap permP/permQ as before. ACT: 0 none, 1 gelu, 2 sigmoid.
// Tile 128x128x16, 256 threads (8 warps, each 64x32 via m16n8k8 frags).
// M,N multiples of 128; K multiple of 16 (true for all calls here).
// ---------------------------------------------------------------------------
template<int BLAYOUT, int ACT>
__global__ void __launch_bounds__(256)
gemm_tc(const float* __restrict__ A, const float* __restrict__ B,
        const float* __restrict__ bias, const float* __restrict__ resid,
        float* __restrict__ C,
        int M, int N, int K, int lda, int ldb,
        long long bA, long long bB, long long bC,
        float alpha, int permP, int permQ)
{
    const int z  = blockIdx.z;
    const float* Ab = A + (long long)z * bA;
    const float* Bb = B + (long long)z * bB;
    const int m0 = blockIdx.y * 128;
    const int n0 = blockIdx.x * 128;

    // As: [m][k] stride 20 ; Bs: layout0 [n][k] stride 20, layout1 [k][n] stride 136
    __shared__ float As[2][2560];
    __shared__ float Bs[2][2560];

    const int tid  = threadIdx.x;
    const int lane = tid & 31;
    const int warp = tid >> 5;
    const int warpM = warp >> 2;   // 0..1
    const int warpN = warp & 3;    // 0..3
    const int lr = lane >> 2;      // 0..7
    const int lc = lane & 3;       // 0..3

    // ---- loader index precompute ----
    const int a_m  = tid >> 2;           // 0..63 (+64 for i=1)
    const int a_kq = (tid & 3) * 4;      // 0,4,8,12
    const float* Aptr = Ab + (long long)(m0 + a_m) * lda + a_kq;

    const float* Bptr;
    int b1_k = 0, b1_nq = 0;
    if (BLAYOUT == 0) {
        Bptr = Bb + (long long)(n0 + a_m) * ldb + a_kq;
    } else {
        b1_k  = tid >> 5;          // 0..7 (+8 for i=1)
        b1_nq = (tid & 31) * 4;    // 0..124
        Bptr = Bb + (long long)b1_k * ldb + n0 + b1_nq;
    }

    float acc[4][4][4];
    #pragma unroll
    for (int a = 0; a < 4; a++)
        #pragma unroll
        for (int b = 0; b < 4; b++)
            #pragma unroll
            for (int c = 0; c < 4; c++) acc[a][b][c] = 0.f;

    const int nkt = K >> 4;

    // ---- load tile 0 ----
    {
        #pragma unroll
        for (int i = 0; i < 2; i++) {
            float4 v = *(const float4*)(Aptr + (long long)i * 64 * lda);
            float4 w; w.x=f2tf_f(v.x); w.y=f2tf_f(v.y); w.z=f2tf_f(v.z); w.w=f2tf_f(v.w);
            *(float4*)(&As[0][(a_m + 64*i)*20 + a_kq]) = w;
        }
        if (BLAYOUT == 0) {
            #pragma unroll
            for (int i = 0; i < 2; i++) {
                float4 v = *(const float4*)(Bptr + (long long)i * 64 * ldb);
                float4 w; w.x=f2tf_f(v.x); w.y=f2tf_f(v.y); w.z=f2tf_f(v.z); w.w=f2tf_f(v.w);
                *(float4*)(&Bs[0][(a_m + 64*i)*20 + a_kq]) = w;
            }
        } else {
            #pragma unroll
            for (int i = 0; i < 2; i++) {
                float4 v = *(const float4*)(Bptr + (long long)i * 8 * ldb);
                float4 w; w.x=f2tf_f(v.x); w.y=f2tf_f(v.y); w.z=f2tf_f(v.z); w.w=f2tf_f(v.w);
                *(float4*)(&Bs[0][(b1_k + 8*i)*136 + b1_nq]) = w;
            }
        }
    }
    __syncthreads();

    int buf = 0;
    for (int kt = 0; kt < nkt; kt++) {
        const bool more = (kt + 1 < nkt);
        float4 av[2], bv[2];
        if (more) {
            const long long ka = (long long)(kt + 1) * 16;
            #pragma unroll
            for (int i = 0; i < 2; i++)
                av[i] = *(const float4*)(Aptr + (long long)i * 64 * lda + ka);
            if (BLAYOUT == 0) {
                #pragma unroll
                for (int i = 0; i < 2; i++)
                    bv[i] = *(const float4*)(Bptr + (long long)i * 64 * ldb + ka);
            } else {
                #pragma unroll
                for (int i = 0; i < 2; i++)
                    bv[i] = *(const float4*)(Bptr + ((long long)i * 8 + ka) * ldb);
            }
        }

        // ---- compute 2 k8 steps ----
        const float* Asb = As[buf];
        const float* Bsb = Bs[buf];
        #pragma unroll
        for (int k8 = 0; k8 < 2; k8++) {
            unsigned af[4][4], bf[4][2];
            #pragma unroll
            for (int mt = 0; mt < 4; mt++) {
                const int r = warpM*64 + mt*16 + lr;
                const int c = k8*8 + lc;
                af[mt][0] = __float_as_uint(Asb[r*20 + c]);
                af[mt][1] = __float_as_uint(Asb[(r+8)*20 + c]);
                af[mt][2] = __float_as_uint(Asb[r*20 + c + 4]);
                af[mt][3] = __float_as_uint(Asb[(r+8)*20 + c + 4]);
            }
            #pragma unroll
            for (int nt = 0; nt < 4; nt++) {
                if (BLAYOUT == 0) {
                    const int nn = warpN*32 + nt*8 + lr;
                    const int c  = k8*8 + lc;
                    bf[nt][0] = __float_as_uint(Bsb[nn*20 + c]);
                    bf[nt][1] = __float_as_uint(Bsb[nn*20 + c + 4]);
                } else {
                    const int kk = k8*8 + lc;
                    const int nn = warpN*32 + nt*8 + lr;
                    bf[nt][0] = __float_as_uint(Bsb[kk*136 + nn]);
                    bf[nt][1] = __float_as_uint(Bsb[(kk+4)*136 + nn]);
                }
            }
            #pragma unroll
            for (int mt = 0; mt < 4; mt++)
                #pragma unroll
                for (int nt = 0; nt < 4; nt++) {
                    asm volatile(
                        "mma.sync.aligned.m16n8k8.row.col.f32.tf32.tf32.f32 "
                        "{%0,%1,%2,%3}, {%4,%5,%6,%7}, {%8,%9}, {%0,%1,%2,%3};"
                        : "+f"(acc[mt][nt][0]), "+f"(acc[mt][nt][1]),
                          "+f"(acc[mt][nt][2]), "+f"(acc[mt][nt][3])
                        : "r"(af[mt][0]), "r"(af[mt][1]), "r"(af[mt][2]), "r"(af[mt][3]),
                          "r"(bf[nt][0]), "r"(bf[nt][1]));
                }
        }

        if (more) {
            const int nb = buf ^ 1;
            #pragma unroll
            for (int i = 0; i < 2; i++) {
                float4 w; w.x=f2tf_f(av[i].x); w.y=f2tf_f(av[i].y);
                w.z=f2tf_f(av[i].z); w.w=f2tf_f(av[i].w);
                *(float4*)(&As[nb][(a_m + 64*i)*20 + a_kq]) = w;
            }
            if (BLAYOUT == 0) {
                #pragma unroll
                for (int i = 0; i < 2; i++) {
                    float4 w; w.x=f2tf_f(bv[i].x); w.y=f2tf_f(bv[i].y);
                    w.z=f2tf_f(bv[i].z); w.w=f2tf_f(bv[i].w);
                    *(float4*)(&Bs[nb][(a_m + 64*i)*20 + a_kq]) = w;
                }
            } else {
                #pragma unroll
                for (int i = 0; i < 2; i++) {
                    float4 w; w.x=f2tf_f(bv[i].x); w.y=f2tf_f(bv[i].y);
                    w.z=f2tf_f(bv[i].z); w.w=f2tf_f(bv[i].w);
                    *(float4*)(&Bs[nb][(b1_k + 8*i)*136 + b1_nq]) = w;
                }
            }
            __syncthreads();
            buf = nb;
        }
    }

    // ---- epilogue ----
    #pragma unroll
    for (int mt = 0; mt < 4; mt++) {
        #pragma unroll
        for (int h = 0; h < 2; h++) {
            const int gm = m0 + warpM*64 + mt*16 + lr + h*8;
            const int rm = (permP > 0) ? ((gm % permP) * permQ + gm / permP) : gm;
            const long long base = (long long)z * bC + (long long)rm * N;
            #pragma unroll
            for (int nt = 0; nt < 4; nt++) {
                const int gn = n0 + warpN*32 + nt*8 + 2*lc;
                float v0 = acc[mt][nt][2*h+0] * alpha;
                float v1 = acc[mt][nt][2*h+1] * alpha;
                if (bias)  { v0 += bias[gn]; v1 += bias[gn+1]; }
                if (resid) { v0 += resid[base + gn]; v1 += resid[base + gn + 1]; }
                if (ACT == 1) { v0 = gelu_exact(v0); v1 = gelu_exact(v1); }
                else if (ACT == 2) {
                    v0 = 1.0f / (1.0f + expf(-v0));
                    v1 = 1.0f / (1.0f + expf(-v1));
                }
                float2 o; o.x = v0; o.y = v1;
                *(float2*)(&C[base + gn]) = o;
            }
        }
    }
}

// ---------------------------------------------------------------------------
// LayerNorm over D=1024
// ---------------------------------------------------------------------------
__global__ void ln_k(const float* __restrict__ x, const float* __restrict__ g,
                     const float* __restrict__ b, float* __restrict__ y)
{
    const long long row = blockIdx.x;
    const float* xr = x + row * D_MODEL;
    float* yr = y + row * D_MODEL;
    const int t = threadIdx.x;

    float v[4], s = 0.f, s2 = 0.f;
    #pragma unroll
    for (int i = 0; i < 4; i++) {
        v[i] = xr[t + i * 256];
        s  += v[i];
        s2 += v[i] * v[i];
    }
    #pragma unroll
    for (int o = 16; o > 0; o >>= 1) {
        s  += __shfl_xor_sync(0xFFFFFFFFu, s,  o);
        s2 += __shfl_xor_sync(0xFFFFFFFFu, s2, o);
    }
    __shared__ float shs[8], shs2[8];
    if ((t & 31) == 0) { shs[t >> 5] = s; shs2[t >> 5] = s2; }
    __syncthreads();
    float S = 0.f, S2 = 0.f;
    #pragma unroll
    for (int w = 0; w < 8; w++) { S += shs[w]; S2 += shs2[w]; }

    const float mean = S * (1.0f / D_MODEL);
    const float var  = S2 * (1.0f / D_MODEL) - mean * mean;
    const float inv  = rsqrtf(var + 1e-5f);
    #pragma unroll
    for (int i = 0; i < 4; i++) {
        const int c = t + i * 256;
        yr[c] = (v[i] - mean) * inv * g[c] + b[c];
    }
}

// ---------------------------------------------------------------------------
// Row softmax (optionally + log(prev_mask + 1e-6))
// ---------------------------------------------------------------------------
__global__ void softmax_k(float* __restrict__ s, const float* __restrict__ pm,
                          int cols)
{
    const long long row = blockIdx.x;
    float* r = s + row * cols;
    const float* pmr = pm ? pm + row * cols : nullptr;
    const int t = threadIdx.x;
    const int nc = cols >> 8;

    float lv[16];
    float mx = -1e30f;
    for (int i = 0; i < nc; i++) {
        float v = r[t + (i << 8)];
        if (pmr) v += logf(pmr[t + (i << 8)] + 1e-6f);
        lv[i] = v;
        mx = fmaxf(mx, v);
    }
    #pragma unroll
    for (int o = 16; o > 0; o >>= 1)
        mx = fmaxf(mx, __shfl_xor_sync(0xFFFFFFFFu, mx, o));
    __shared__ float shm[8], shsum[8];
    if ((t & 31) == 0) shm[t >> 5] = mx;
    __syncthreads();
    float MX = shm[0];
    #pragma unroll
    for (int w = 1; w < 8; w++) MX = fmaxf(MX, shm[w]);

    float sum = 0.f;
    for (int i = 0; i < nc; i++) {
        const float e = expf(lv[i] - MX);
        lv[i] = e;
        sum += e;
    }
    #pragma unroll
    for (int o = 16; o > 0; o >>= 1)
        sum += __shfl_xor_sync(0xFFFFFFFFu, sum, o);
    if ((t & 31) == 0) shsum[t >> 5] = sum;
    __syncthreads();
    float SUM = 0.f;
    #pragma unroll
    for (int w = 0; w < 8; w++) SUM += shsum[w];

    const float inv = 1.0f / SUM;
    for (int i = 0; i < nc; i++) r[t + (i << 8)] = lv[i] * inv;
}

// ---------------------------------------------------------------------------
// Repack kernels
// ---------------------------------------------------------------------------
__global__ void repack_qkv_k(const float* __restrict__ qkv, float* __restrict__ pack)
{
    const long long gid = (long long)blockIdx.x * 256 + threadIdx.x;
    const int d   = gid & 127;
    const int l   = (gid >> 7) & 255;
    const int bh  = (gid >> 15) & 63;
    const int sec = (int)(gid >> 21);
    const int b = bh >> 3, h = bh & 7;
    const long long in = (long long)(l * BATCH + b) * (3 * D_MODEL)
                         + sec * D_MODEL + h * HDIM + d;
    pack[gid] = qkv[in];
}

__global__ void repack_o_k(const float* __restrict__ o, float* __restrict__ out)
{
    const long long gid = (long long)blockIdx.x * 256 + threadIdx.x;
    const int c = gid & 1023;
    const int m = (int)(gid >> 10);
    const int l = m >> 3, b = m & 7;
    const int h = c >> 7, d = c & 127;
    out[gid] = o[((long long)(b * 8 + h) * 256 + l) * 128 + d];
}

__global__ void repack_qmask_k(const float* __restrict__ q, float* __restrict__ out)
{
    const long long gid = (long long)blockIdx.x * 256 + threadIdx.x;
    const int d = gid & 1023;
    const int m = (int)(gid >> 10);
    const int b = m >> 8, qq = m & 255;
    out[gid] = q[(long long)(qq * 8 + b) * 1024 + d];
}

// ---------------------------------------------------------------------------
// kernel_launch
// ---------------------------------------------------------------------------
extern "C" void kernel_launch(void* const* d_in, const int* in_sizes, int n_in,
                              void* d_out, int out_size)
{
    const float* query    = (const float*)d_in[0];
    const float* memory   = (const float*)d_in[1];
    const float* prevmask = (const float*)d_in[2];
    const float* sa_in_w  = (const float*)d_in[5];
    const float* sa_in_b  = (const float*)d_in[6];
    const float* sa_out_w = (const float*)d_in[7];
    const float* sa_out_b = (const float*)d_in[8];
    const float* ln1_g = (const float*)d_in[9];
    const float* ln1_b = (const float*)d_in[10];
    const float* ln2_g = (const float*)d_in[11];
    const float* ln2_b = (const float*)d_in[12];
    const float* ln3_g = (const float*)d_in[13];
    const float* ln3_b = (const float*)d_in[14];
    const float* wq = (const float*)d_in[15];
    const float* bq = (const float*)d_in[16];
    const float* wk = (const float*)d_in[17];
    const float* bk = (const float*)d_in[18];
    const float* wv = (const float*)d_in[19];
    const float* bv = (const float*)d_in[20];
    const float* wo = (const float*)d_in[21];
    const float* bo = (const float*)d_in[22];
    const float* w1 = (const float*)d_in[23];
    const float* b1 = (const float*)d_in[24];
    const float* w2 = (const float*)d_in[25];
    const float* b2 = (const float*)d_in[26];
    const float* mask_w = (const float*)d_in[27];
    const float* mask_b = (const float*)d_in[28];

    float* scr = nullptr;
    cudaGetSymbolAddress((void**)&scr, g_scratch);

    float* gx    = scr + OFF_X;
    float* gqkv  = scr + OFF_QKV;
    float* gq    = scr + OFF_PACK;
    float* gk    = scr + OFF_PACK + 2097152LL;
    float* gv    = scr + OFF_PACK + 4194304LL;
    float* gsc   = scr + OFF_SCORES;
    float* go    = scr + OFF_O;
    float* gorep = scr + OFF_OREP;
    float* gq1   = scr + OFF_Q1;
    float* gQc   = scr + OFF_QC;
    float* gK    = scr + OFF_K;
    float* gV    = scr + OFF_V;
    float* gq2   = scr + OFF_Q2;
    float* gh    = scr + OFF_H;
    float* gqm   = scr + OFF_QM;

    float* out_q = (float*)d_out;
    float* out_m = out_q + (long long)M_TOK * D_MODEL;

    const float inv_sqrt_hd = 0.088388347648318447f;
    const float inv_sqrt_d  = 0.03125f;

    // 1. ln1(query)
    ln_k<<<M_TOK, 256>>>(query, ln1_g, ln1_b, gx);

    // 2. QKV projection
    gemm_tc<0,0><<<dim3(24,16,1), 256>>>(gx, sa_in_w, sa_in_b, nullptr, gqkv,
        M_TOK, 3*D_MODEL, D_MODEL, D_MODEL, D_MODEL, 0, 0, 0, 1.0f, 0, 0);

    // 3. pack q,k,v
    repack_qkv_k<<<24576, 256>>>(gqkv, gq);

    // 4. self-attn scores (batched 64)
    gemm_tc<0,0><<<dim3(2,2,64), 256>>>(gq, gk, nullptr, nullptr, gsc,
        NQ, NQ, HDIM, HDIM, HDIM, 256LL*128, 256LL*128, 256LL*256,
        inv_sqrt_hd, 0, 0);

    // 5. softmax
    softmax_k<<<64*256, 256>>>(gsc, nullptr, 256);

    // 6. o = attn @ v
    gemm_tc<1,0><<<dim3(1,2,64), 256>>>(gsc, gv, nullptr, nullptr, go,
        NQ, HDIM, NQ, NQ, HDIM, 256LL*256, 256LL*128, 256LL*128, 1.0f, 0, 0);

    // 7. repack o
    repack_o_k<<<8192, 256>>>(go, gorep);

    // 8. self out-proj + residual
    gemm_tc<0,0><<<dim3(8,16,1), 256>>>(gorep, sa_out_w, sa_out_b, query, gq1,
        M_TOK, D_MODEL, D_MODEL, D_MODEL, D_MODEL, 0, 0, 0, 1.0f, 0, 0);

    // 9. ln2
    ln_k<<<M_TOK, 256>>>(gq1, ln2_g, ln2_b, gx);

    // 10. Q proj -> [B,NQ,D]
    gemm_tc<0,0><<<dim3(8,16,1), 256>>>(gx, wq, bq, nullptr, gQc,
        M_TOK, D_MODEL, D_MODEL, D_MODEL, D_MODEL, 0, 0, 0, 1.0f, 8, 256);

    // 11/12. K,V proj -> [B,S,D]
    gemm_tc<0,0><<<dim3(8,256,1), 256>>>(memory, wk, bk, nullptr, gK,
        M_MEM, D_MODEL, D_MODEL, D_MODEL, D_MODEL, 0, 0, 0, 1.0f, 8, 4096);
    gemm_tc<0,0><<<dim3(8,256,1), 256>>>(memory, wv, bv, nullptr, gV,
        M_MEM, D_MODEL, D_MODEL, D_MODEL, D_MODEL, 0, 0, 0, 1.0f, 8, 4096);

    // 13. cross scores
    gemm_tc<0,0><<<dim3(32,2,8), 256>>>(gQc, gK, nullptr, nullptr, gsc,
        NQ, SEQ_S, D_MODEL, D_MODEL, D_MODEL,
        256LL*1024, 4096LL*1024, 256LL*4096, inv_sqrt_d, 0, 0);

    // 14. softmax + log(prev_mask)
    softmax_k<<<BATCH*NQ, 256>>>(gsc, prevmask, SEQ_S);

    // 15. attn_out = attn @ V
    gemm_tc<1,0><<<dim3(8,2,8), 256>>>(gsc, gV, nullptr, nullptr, go,
        NQ, D_MODEL, SEQ_S, SEQ_S, D_MODEL,
        256LL*4096, 4096LL*1024, 256LL*1024, 1.0f, 0, 0);

    // 16. cross out-proj + residual -> [NQ,B,D]
    gemm_tc<0,0><<<dim3(8,16,1), 256>>>(go, wo, bo, gq1, gq2,
        M_TOK, D_MODEL, D_MODEL, D_MODEL, D_MODEL, 0, 0, 0, 1.0f, 256, 8);

    // 17. ln3
    ln_k<<<M_TOK, 256>>>(gq2, ln3_g, ln3_b, gx);

    // 18. FFN1 + GELU
    gemm_tc<0,1><<<dim3(32,16,1), 256>>>(gx, w1, b1, nullptr, gh,
        M_TOK, FF_DIM, D_MODEL, D_MODEL, D_MODEL, 0, 0, 0, 1.0f, 0, 0);

    // 19. FFN2 + residual -> final query
    gemm_tc<0,0><<<dim3(8,16,1), 256>>>(gh, w2, b2, gq2, out_q,
        M_TOK, D_MODEL, FF_DIM, FF_DIM, FF_DIM, 0, 0, 0, 1.0f, 0, 0);

    // 20. gather final query to [B,NQ,D]
    repack_qmask_k<<<8192, 256>>>(out_q, gqm);

    // 21. mask logits + sigmoid
    gemm_tc<0,2><<<dim3(32,16,1), 256>>>(gqm, mask_w, mask_b, nullptr, out_m,
        M_TOK, SEQ_S, D_MODEL, D_MODEL, D_MODEL, 0, 0, 0, 1.0f, 0, 0);
}

// round 4
// speedup vs baseline: 3.1186x; 1.1657x over previous
#include <cuda_runtime.h>
#include <cuda_bf16.h>
#include <math.h>

// ---------------------------------------------------------------------------
// Problem constants
// ---------------------------------------------------------------------------
#define D_MODEL 1024
#define NHEAD   8
#define HDIM    128
#define NQ      256
#define BATCH   8
#define SEQ_S   4096
#define FF_DIM  4096
#define M_TOK   (NQ*BATCH)       // 2048
#define M_MEM   (SEQ_S*BATCH)    // 32768

// ---------------------------------------------------------------------------
// Scratch
// ---------------------------------------------------------------------------
#define OFF_X      0LL
#define OFF_QKV    (OFF_X    + 2097152LL)
#define OFF_PACK   (OFF_QKV  + 6291456LL)
#define OFF_SCORES (OFF_PACK + 6291456LL)
#define OFF_O      (OFF_SCORES + 8388608LL)
#define OFF_OREP   (OFF_O    + 2097152LL)
#define OFF_Q1     (OFF_OREP + 2097152LL)
#define OFF_QC     (OFF_Q1   + 2097152LL)
#define OFF_K      (OFF_QC   + 2097152LL)
#define OFF_V      (OFF_K    + 33554432LL)
#define OFF_Q2     (OFF_V    + 33554432LL)
#define OFF_H      (OFF_Q2   + 2097152LL)
#define OFF_QM     (OFF_H    + 8388608LL)
#define OFF_WCVT   (OFF_QM   + 2097152LL)   // rounded weights, 20971520
#define OFF_MEMR   (OFF_WCVT + 20971520LL)  // rounded memory, 33554432
#define SCRATCH_TOTAL (OFF_MEMR + 33554432LL)

__device__ float g_scratch[SCRATCH_TOTAL];

// weight sub-offsets inside WCVT (floats)
#define W_SAIN   0LL
#define W_SAOUT  3145728LL
#define W_Q      4194304LL
#define W_K      5242880LL
#define W_V      6291456LL
#define W_O      7340032LL
#define W_1      8388608LL
#define W_2      12582912LL
#define W_MASK   16777216LL

// ---------------------------------------------------------------------------
// Helpers
// ---------------------------------------------------------------------------
__device__ __forceinline__ float gelu_exact(float x) {
    return 0.5f * x * (1.0f + erff(x * 0.70710678118654752f));
}
__device__ __forceinline__ float f2tf_f(float x) {
    unsigned u;
    asm("cvt.rna.tf32.f32 %0, %1;" : "=r"(u) : "f"(x));
    return __uint_as_float(u);
}

// ---------------------------------------------------------------------------
// tf32 tensor-core batched GEMM with 4-stage cp.async pipeline.
//   C = act( alpha * A @ op(B) + bias + resid )
//   A row-major [M,K] (values already tf32-rounded).
//   BLAYOUT 0: B is [N,K] (A@B^T). BLAYOUT 1: B is [K,N].
//   RND: round output to tf32 (for values feeding another GEMM).
//   Tile 128x128x16, 256 threads, 8 warps x (64x32). K multiple of 16, >= 64.
// Dynamic smem: 4 stages * (2560 + 2560) floats = 81920 B.
// ---------------------------------------------------------------------------
#define GSTAGES 4
#define GSMEM_BYTES (GSTAGES * 2560 * 2 * 4)

template<int BLAYOUT, int ACT, int RND>
__global__ void __launch_bounds__(256, 2)
gemm_tc(const float* __restrict__ A, const float* __restrict__ B,
        const float* __restrict__ bias, const float* __restrict__ resid,
        float* __restrict__ C,
        int M, int N, int K, int lda, int ldb,
        long long bA, long long bB, long long bC,
        float alpha, int permP, int permQ)
{
    extern __shared__ float smem[];
    float* As = smem;                     // [GSTAGES][2560]  (m-major, stride 20)
    float* Bs = smem + GSTAGES * 2560;    // [GSTAGES][2560]  (stride 20 or 136)

    const int z  = blockIdx.z;
    const float* Ab = A + (long long)z * bA;
    const float* Bb = B + (long long)z * bB;
    const int m0 = blockIdx.y * 128;
    const int n0 = blockIdx.x * 128;

    const int tid  = threadIdx.x;
    const int lane = tid & 31;
    const int warp = tid >> 5;
    const int warpM = warp >> 2;
    const int warpN = warp & 3;
    const int lr = lane >> 2;
    const int lc = lane & 3;

    const int a_m  = tid >> 2;           // 0..63 (+64)
    const int a_kq = (tid & 3) * 4;
    const float* Aptr = Ab + (long long)(m0 + a_m) * lda + a_kq;

    const float* Bptr;
    int b1_k = 0, b1_nq = 0;
    if (BLAYOUT == 0) {
        Bptr = Bb + (long long)(n0 + a_m) * ldb + a_kq;
    } else {
        b1_k  = tid >> 5;
        b1_nq = (tid & 31) * 4;
        Bptr = Bb + (long long)b1_k * ldb + n0 + b1_nq;
    }

    const unsigned sAu = (unsigned)__cvta_generic_to_shared(As);
    const unsigned sBu = (unsigned)__cvta_generic_to_shared(Bs);
    const unsigned dA0 = sAu + (unsigned)(a_m * 20 + a_kq) * 4u;
    const unsigned dB0 = (BLAYOUT == 0)
        ? sBu + (unsigned)(a_m * 20 + a_kq) * 4u
        : sBu + (unsigned)(b1_k * 136 + b1_nq) * 4u;

    const int nkt = K >> 4;

    auto issue = [&](int kt, int slot) {
        const long long ka = (long long)kt * 16;
        const unsigned so = (unsigned)slot * 2560u * 4u;
        #pragma unroll
        for (int i = 0; i < 2; i++) {
            const float* g = Aptr + (long long)i * 64 * lda + ka;
            unsigned d = dA0 + so + (unsigned)(i * 64 * 20) * 4u;
            asm volatile("cp.async.cg.shared.global [%0], [%1], 16;\n"
                         :: "r"(d), "l"(g));
        }
        if (BLAYOUT == 0) {
            #pragma unroll
            for (int i = 0; i < 2; i++) {
                const float* g = Bptr + (long long)i * 64 * ldb + ka;
                unsigned d = dB0 + so + (unsigned)(i * 64 * 20) * 4u;
                asm volatile("cp.async.cg.shared.global [%0], [%1], 16;\n"
                             :: "r"(d), "l"(g));
            }
        } else {
            #pragma unroll
            for (int i = 0; i < 2; i++) {
                const float* g = Bptr + (ka + (long long)i * 8) * ldb;
                unsigned d = dB0 + so + (unsigned)(i * 8 * 136) * 4u;
                asm volatile("cp.async.cg.shared.global [%0], [%1], 16;\n"
                             :: "r"(d), "l"(g));
            }
        }
        asm volatile("cp.async.commit_group;\n");
    };

    float acc[4][4][4];
    #pragma unroll
    for (int a = 0; a < 4; a++)
        #pragma unroll
        for (int b = 0; b < 4; b++)
            #pragma unroll
            for (int c = 0; c < 4; c++) acc[a][b][c] = 0.f;

    // prologue: 3 groups
    #pragma unroll
    for (int s = 0; s < GSTAGES - 1; s++) {
        if (s < nkt) issue(s, s);
        else asm volatile("cp.async.commit_group;\n");
    }

    for (int kt = 0; kt < nkt; kt++) {
        asm volatile("cp.async.wait_group %0;\n" :: "n"(GSTAGES - 2));
        __syncthreads();

        const int nx = kt + GSTAGES - 1;
        if (nx < nkt) issue(nx, nx & (GSTAGES - 1));
        else asm volatile("cp.async.commit_group;\n");

        const float* Asb = As + (kt & (GSTAGES - 1)) * 2560;
        const float* Bsb = Bs + (kt & (GSTAGES - 1)) * 2560;

        #pragma unroll
        for (int k8 = 0; k8 < 2; k8++) {
            unsigned af[4][4], bf[4][2];
            #pragma unroll
            for (int mt = 0; mt < 4; mt++) {
                const int r = warpM*64 + mt*16 + lr;
                const int c = k8*8 + lc;
                af[mt][0] = __float_as_uint(Asb[r*20 + c]);
                af[mt][1] = __float_as_uint(Asb[(r+8)*20 + c]);
                af[mt][2] = __float_as_uint(Asb[r*20 + c + 4]);
                af[mt][3] = __float_as_uint(Asb[(r+8)*20 + c + 4]);
            }
            #pragma unroll
            for (int nt = 0; nt < 4; nt++) {
                if (BLAYOUT == 0) {
                    const int nn = warpN*32 + nt*8 + lr;
                    const int c  = k8*8 + lc;
                    bf[nt][0] = __float_as_uint(Bsb[nn*20 + c]);
                    bf[nt][1] = __float_as_uint(Bsb[nn*20 + c + 4]);
                } else {
                    const int kk = k8*8 + lc;
                    const int nn = warpN*32 + nt*8 + lr;
                    bf[nt][0] = __float_as_uint(Bsb[kk*136 + nn]);
                    bf[nt][1] = __float_as_uint(Bsb[(kk+4)*136 + nn]);
                }
            }
            #pragma unroll
            for (int mt = 0; mt < 4; mt++)
                #pragma unroll
                for (int nt = 0; nt < 4; nt++) {
                    asm volatile(
                        "mma.sync.aligned.m16n8k8.row.col.f32.tf32.tf32.f32 "
                        "{%0,%1,%2,%3}, {%4,%5,%6,%7}, {%8,%9}, {%0,%1,%2,%3};"
                        : "+f"(acc[mt][nt][0]), "+f"(acc[mt][nt][1]),
                          "+f"(acc[mt][nt][2]), "+f"(acc[mt][nt][3])
                        : "r"(af[mt][0]), "r"(af[mt][1]), "r"(af[mt][2]), "r"(af[mt][3]),
                          "r"(bf[nt][0]), "r"(bf[nt][1]));
                }
        }
    }

    // epilogue
    #pragma unroll
    for (int mt = 0; mt < 4; mt++) {
        #pragma unroll
        for (int h = 0; h < 2; h++) {
            const int gm = m0 + warpM*64 + mt*16 + lr + h*8;
            const int rm = (permP > 0) ? ((gm % permP) * permQ + gm / permP) : gm;
            const long long base = (long long)z * bC + (long long)rm * N;
            #pragma unroll
            for (int nt = 0; nt < 4; nt++) {
                const int gn = n0 + warpN*32 + nt*8 + 2*lc;
                float v0 = acc[mt][nt][2*h+0] * alpha;
                float v1 = acc[mt][nt][2*h+1] * alpha;
                if (bias)  { v0 += bias[gn]; v1 += bias[gn+1]; }
                if (resid) { v0 += resid[base + gn]; v1 += resid[base + gn + 1]; }
                if (ACT == 1) { v0 = gelu_exact(v0); v1 = gelu_exact(v1); }
                else if (ACT == 2) {
                    v0 = 1.0f / (1.0f + expf(-v0));
                    v1 = 1.0f / (1.0f + expf(-v1));
                }
                if (RND) { v0 = f2tf_f(v0); v1 = f2tf_f(v1); }
                float2 o; o.x = v0; o.y = v1;
                *(float2*)(&C[base + gn]) = o;
            }
        }
    }
}

// ---------------------------------------------------------------------------
// tf32 rounding pass (float4)
// ---------------------------------------------------------------------------
__global__ void round4_k(const float* __restrict__ in, float* __restrict__ out,
                         int n4)
{
    const int i = blockIdx.x * 256 + threadIdx.x;
    if (i < n4) {
        float4 v = ((const float4*)in)[i];
        v.x = f2tf_f(v.x); v.y = f2tf_f(v.y);
        v.z = f2tf_f(v.z); v.w = f2tf_f(v.w);
        ((float4*)out)[i] = v;
    }
}

// ---------------------------------------------------------------------------
// LayerNorm over D=1024 (output tf32-rounded: always feeds a GEMM A operand)
// ---------------------------------------------------------------------------
__global__ void ln_k(const float* __restrict__ x, const float* __restrict__ g,
                     const float* __restrict__ b, float* __restrict__ y)
{
    const long long row = blockIdx.x;
    const float* xr = x + row * D_MODEL;
    float* yr = y + row * D_MODEL;
    const int t = threadIdx.x;

    float v[4], s = 0.f, s2 = 0.f;
    #pragma unroll
    for (int i = 0; i < 4; i++) {
        v[i] = xr[t + i * 256];
        s  += v[i];
        s2 += v[i] * v[i];
    }
    #pragma unroll
    for (int o = 16; o > 0; o >>= 1) {
        s  += __shfl_xor_sync(0xFFFFFFFFu, s,  o);
        s2 += __shfl_xor_sync(0xFFFFFFFFu, s2, o);
    }
    __shared__ float shs[8], shs2[8];
    if ((t & 31) == 0) { shs[t >> 5] = s; shs2[t >> 5] = s2; }
    __syncthreads();
    float S = 0.f, S2 = 0.f;
    #pragma unroll
    for (int w = 0; w < 8; w++) { S += shs[w]; S2 += shs2[w]; }

    const float mean = S * (1.0f / D_MODEL);
    const float var  = S2 * (1.0f / D_MODEL) - mean * mean;
    const float inv  = rsqrtf(var + 1e-5f);
    #pragma unroll
    for (int i = 0; i < 4; i++) {
        const int c = t + i * 256;
        yr[c] = f2tf_f((v[i] - mean) * inv * g[c] + b[c]);
    }
}

// ---------------------------------------------------------------------------
// Row softmax (optionally + log(prev_mask + 1e-6)); output tf32-rounded
// ---------------------------------------------------------------------------
__global__ void softmax_k(float* __restrict__ s, const float* __restrict__ pm,
                          int cols)
{
    const long long row = blockIdx.x;
    float* r = s + row * cols;
    const float* pmr = pm ? pm + row * cols : nullptr;
    const int t = threadIdx.x;
    const int nc = cols >> 8;

    float lv[16];
    float mx = -1e30f;
    for (int i = 0; i < nc; i++) {
        float v = r[t + (i << 8)];
        if (pmr) v += logf(pmr[t + (i << 8)] + 1e-6f);
        lv[i] = v;
        mx = fmaxf(mx, v);
    }
    #pragma unroll
    for (int o = 16; o > 0; o >>= 1)
        mx = fmaxf(mx, __shfl_xor_sync(0xFFFFFFFFu, mx, o));
    __shared__ float shm[8], shsum[8];
    if ((t & 31) == 0) shm[t >> 5] = mx;
    __syncthreads();
    float MX = shm[0];
    #pragma unroll
    for (int w = 1; w < 8; w++) MX = fmaxf(MX, shm[w]);

    float sum = 0.f;
    for (int i = 0; i < nc; i++) {
        const float e = expf(lv[i] - MX);
        lv[i] = e;
        sum += e;
    }
    #pragma unroll
    for (int o = 16; o > 0; o >>= 1)
        sum += __shfl_xor_sync(0xFFFFFFFFu, sum, o);
    if ((t & 31) == 0) shsum[t >> 5] = sum;
    __syncthreads();
    float SUM = 0.f;
    #pragma unroll
    for (int w = 0; w < 8; w++) SUM += shsum[w];

    const float inv = 1.0f / SUM;
    for (int i = 0; i < nc; i++) r[t + (i << 8)] = f2tf_f(lv[i] * inv);
}

// ---------------------------------------------------------------------------
// Repack kernels (outputs tf32-rounded where they feed GEMM operands)
// ---------------------------------------------------------------------------
__global__ void repack_qkv_k(const float* __restrict__ qkv, float* __restrict__ pack)
{
    const long long gid = (long long)blockIdx.x * 256 + threadIdx.x;
    const int d   = gid & 127;
    const int l   = (gid >> 7) & 255;
    const int bh  = (gid >> 15) & 63;
    const int sec = (int)(gid >> 21);
    const int b = bh >> 3, h = bh & 7;
    const long long in = (long long)(l * BATCH + b) * (3 * D_MODEL)
                         + sec * D_MODEL + h * HDIM + d;
    pack[gid] = f2tf_f(qkv[in]);
}

__global__ void repack_o_k(const float* __restrict__ o, float* __restrict__ out)
{
    const long long gid = (long long)blockIdx.x * 256 + threadIdx.x;
    const int c = gid & 1023;
    const int m = (int)(gid >> 10);
    const int l = m >> 3, b = m & 7;
    const int h = c >> 7, d = c & 127;
    out[gid] = f2tf_f(o[((long long)(b * 8 + h) * 256 + l) * 128 + d]);
}

__global__ void repack_qmask_k(const float* __restrict__ q, float* __restrict__ out)
{
    const long long gid = (long long)blockIdx.x * 256 + threadIdx.x;
    const int d = gid & 1023;
    const int m = (int)(gid >> 10);
    const int b = m >> 8, qq = m & 255;
    out[gid] = f2tf_f(q[(long long)(qq * 8 + b) * 1024 + d]);
}

// ---------------------------------------------------------------------------
// kernel_launch
// ---------------------------------------------------------------------------
extern "C" void kernel_launch(void* const* d_in, const int* in_sizes, int n_in,
                              void* d_out, int out_size)
{
    const float* query    = (const float*)d_in[0];
    const float* memory   = (const float*)d_in[1];
    const float* prevmask = (const float*)d_in[2];
    const float* sa_in_w  = (const float*)d_in[5];
    const float* sa_in_b  = (const float*)d_in[6];
    const float* sa_out_w = (const float*)d_in[7];
    const float* sa_out_b = (const float*)d_in[8];
    const float* ln1_g = (const float*)d_in[9];
    const float* ln1_b = (const float*)d_in[10];
    const float* ln2_g = (const float*)d_in[11];
    const float* ln2_b = (const float*)d_in[12];
    const float* ln3_g = (const float*)d_in[13];
    const float* ln3_b = (const float*)d_in[14];
    const float* wq = (const float*)d_in[15];
    const float* bq = (const float*)d_in[16];
    const float* wk = (const float*)d_in[17];
    const float* bk = (const float*)d_in[18];
    const float* wv = (const float*)d_in[19];
    const float* bv = (const float*)d_in[20];
    const float* wo = (const float*)d_in[21];
    const float* bo = (const float*)d_in[22];
    const float* w1 = (const float*)d_in[23];
    const float* b1 = (const float*)d_in[24];
    const float* w2 = (const float*)d_in[25];
    const float* b2 = (const float*)d_in[26];
    const float* mask_w = (const float*)d_in[27];
    const float* mask_b = (const float*)d_in[28];

    float* scr = nullptr;
    cudaGetSymbolAddress((void**)&scr, g_scratch);

    float* gx    = scr + OFF_X;
    float* gqkv  = scr + OFF_QKV;
    float* gq    = scr + OFF_PACK;
    float* gk    = scr + OFF_PACK + 2097152LL;
    float* gv    = scr + OFF_PACK + 4194304LL;
    float* gsc   = scr + OFF_SCORES;
    float* go    = scr + OFF_O;
    float* gorep = scr + OFF_OREP;
    float* gq1   = scr + OFF_Q1;
    float* gQc   = scr + OFF_QC;
    float* gK    = scr + OFF_K;
    float* gV    = scr + OFF_V;
    float* gq2   = scr + OFF_Q2;
    float* gh    = scr + OFF_H;
    float* gqm   = scr + OFF_QM;
    float* wc    = scr + OFF_WCVT;
    float* memr  = scr + OFF_MEMR;

    float* c_sa_in_w  = wc + W_SAIN;
    float* c_sa_out_w = wc + W_SAOUT;
    float* c_wq = wc + W_Q;
    float* c_wk = wc + W_K;
    float* c_wv = wc + W_V;
    float* c_wo = wc + W_O;
    float* c_w1 = wc + W_1;
    float* c_w2 = wc + W_2;
    float* c_mask_w = wc + W_MASK;

    float* out_q = (float*)d_out;
    float* out_m = out_q + (long long)M_TOK * D_MODEL;

    const float inv_sqrt_hd = 0.088388347648318447f;
    const float inv_sqrt_d  = 0.03125f;

    // opt-in dynamic smem for all gemm instantiations (persistent attribute)
    cudaFuncSetAttribute(gemm_tc<0,0,0>, cudaFuncAttributeMaxDynamicSharedMemorySize, GSMEM_BYTES);
    cudaFuncSetAttribute(gemm_tc<1,0,0>, cudaFuncAttributeMaxDynamicSharedMemorySize, GSMEM_BYTES);
    cudaFuncSetAttribute(gemm_tc<0,0,1>, cudaFuncAttributeMaxDynamicSharedMemorySize, GSMEM_BYTES);
    cudaFuncSetAttribute(gemm_tc<1,0,1>, cudaFuncAttributeMaxDynamicSharedMemorySize, GSMEM_BYTES);
    cudaFuncSetAttribute(gemm_tc<0,1,1>, cudaFuncAttributeMaxDynamicSharedMemorySize, GSMEM_BYTES);
    cudaFuncSetAttribute(gemm_tc<0,2,0>, cudaFuncAttributeMaxDynamicSharedMemorySize, GSMEM_BYTES);

    // --- 0. pre-round weights + memory to tf32 ---
    round4_k<<<3072, 256>>>(sa_in_w, c_sa_in_w, 786432);
    round4_k<<<1024, 256>>>(sa_out_w, c_sa_out_w, 262144);
    round4_k<<<1024, 256>>>(wq, c_wq, 262144);
    round4_k<<<1024, 256>>>(wk, c_wk, 262144);
    round4_k<<<1024, 256>>>(wv, c_wv, 262144);
    round4_k<<<1024, 256>>>(wo, c_wo, 262144);
    round4_k<<<4096, 256>>>(w1, c_w1, 1048576);
    round4_k<<<4096, 256>>>(w2, c_w2, 1048576);
    round4_k<<<4096, 256>>>(mask_w, c_mask_w, 1048576);
    round4_k<<<32768, 256>>>(memory, memr, 8388608);

    // 1. ln1(query)
    ln_k<<<M_TOK, 256>>>(query, ln1_g, ln1_b, gx);

    // 2. QKV projection
    gemm_tc<0,0,0><<<dim3(24,16,1), 256, GSMEM_BYTES>>>(gx, c_sa_in_w, sa_in_b, nullptr, gqkv,
        M_TOK, 3*D_MODEL, D_MODEL, D_MODEL, D_MODEL, 0, 0, 0, 1.0f, 0, 0);

    // 3. pack q,k,v (rounds)
    repack_qkv_k<<<24576, 256>>>(gqkv, gq);

    // 4. self-attn scores (batched 64)
    gemm_tc<0,0,0><<<dim3(2,2,64), 256, GSMEM_BYTES>>>(gq, gk, nullptr, nullptr, gsc,
        NQ, NQ, HDIM, HDIM, HDIM, 256LL*128, 256LL*128, 256LL*256,
        inv_sqrt_hd, 0, 0);

    // 5. softmax (rounds)
    softmax_k<<<64*256, 256>>>(gsc, nullptr, 256);

    // 6. o = attn @ v
    gemm_tc<1,0,0><<<dim3(1,2,64), 256, GSMEM_BYTES>>>(gsc, gv, nullptr, nullptr, go,
        NQ, HDIM, NQ, NQ, HDIM, 256LL*256, 256LL*128, 256LL*128, 1.0f, 0, 0);

    // 7. repack o (rounds)
    repack_o_k<<<8192, 256>>>(go, gorep);

    // 8. self out-proj + residual
    gemm_tc<0,0,0><<<dim3(8,16,1), 256, GSMEM_BYTES>>>(gorep, c_sa_out_w, sa_out_b, query, gq1,
        M_TOK, D_MODEL, D_MODEL, D_MODEL, D_MODEL, 0, 0, 0, 1.0f, 0, 0);

    // 9. ln2 (rounds)
    ln_k<<<M_TOK, 256>>>(gq1, ln2_g, ln2_b, gx);

    // 10. Q proj -> [B,NQ,D] (rounds)
    gemm_tc<0,0,1><<<dim3(8,16,1), 256, GSMEM_BYTES>>>(gx, c_wq, bq, nullptr, gQc,
        M_TOK, D_MODEL, D_MODEL, D_MODEL, D_MODEL, 0, 0, 0, 1.0f, 8, 256);

    // 11/12. K,V proj -> [B,S,D] (round)
    gemm_tc<0,0,1><<<dim3(8,256,1), 256, GSMEM_BYTES>>>(memr, c_wk, bk, nullptr, gK,
        M_MEM, D_MODEL, D_MODEL, D_MODEL, D_MODEL, 0, 0, 0, 1.0f, 8, 4096);
    gemm_tc<0,0,1><<<dim3(8,256,1), 256, GSMEM_BYTES>>>(memr, c_wv, bv, nullptr, gV,
        M_MEM, D_MODEL, D_MODEL, D_MODEL, D_MODEL, 0, 0, 0, 1.0f, 8, 4096);

    // 13. cross scores
    gemm_tc<0,0,0><<<dim3(32,2,8), 256, GSMEM_BYTES>>>(gQc, gK, nullptr, nullptr, gsc,
        NQ, SEQ_S, D_MODEL, D_MODEL, D_MODEL,
        256LL*1024, 4096LL*1024, 256LL*4096, inv_sqrt_d, 0, 0);

    // 14. softmax + log(prev_mask) (rounds)
    softmax_k<<<BATCH*NQ, 256>>>(gsc, prevmask, SEQ_S);

    // 15. attn_out = attn @ V (rounds)
    gemm_tc<1,0,1><<<dim3(8,2,8), 256, GSMEM_BYTES>>>(gsc, gV, nullptr, nullptr, go,
        NQ, D_MODEL, SEQ_S, SEQ_S, D_MODEL,
        256LL*4096, 4096LL*1024, 256LL*1024, 1.0f, 0, 0);

    // 16. cross out-proj + residual -> [NQ,B,D]
    gemm_tc<0,0,0><<<dim3(8,16,1), 256, GSMEM_BYTES>>>(go, c_wo, bo, gq1, gq2,
        M_TOK, D_MODEL, D_MODEL, D_MODEL, D_MODEL, 0, 0, 0, 1.0f, 256, 8);

    // 17. ln3 (rounds)
    ln_k<<<M_TOK, 256>>>(gq2, ln3_g, ln3_b, gx);

    // 18. FFN1 + GELU (rounds)
    gemm_tc<0,1,1><<<dim3(32,16,1), 256, GSMEM_BYTES>>>(gx, c_w1, b1, nullptr, gh,
        M_TOK, FF_DIM, D_MODEL, D_MODEL, D_MODEL, 0, 0, 0, 1.0f, 0, 0);

    // 19. FFN2 + residual -> final query (fp32, no round)
    gemm_tc<0,0,0><<<dim3(8,16,1), 256, GSMEM_BYTES>>>(gh, c_w2, b2, gq2, out_q,
        M_TOK, D_MODEL, FF_DIM, FF_DIM, FF_DIM, 0, 0, 0, 1.0f, 0, 0);

    // 20. gather final query to [B,NQ,D] (rounds)
    repack_qmask_k<<<8192, 256>>>(out_q, gqm);

    // 21. mask logits + sigmoid
    gemm_tc<0,2,0><<<dim3(32,16,1), 256, GSMEM_BYTES>>>(gqm, c_mask_w, mask_b, nullptr, out_m,
        M_TOK, SEQ_S, D_MODEL, D_MODEL, D_MODEL, 0, 0, 0, 1.0f, 0, 0);
}

// round 9
// speedup vs baseline: 3.1430x; 1.0078x over previous
#include <cuda_runtime.h>
#include <cuda_bf16.h>
#include <math.h>

// ---------------------------------------------------------------------------
// Problem constants
// ---------------------------------------------------------------------------
#define D_MODEL 1024
#define NHEAD   8
#define HDIM    128
#define NQ      256
#define BATCH   8
#define SEQ_S   4096
#define FF_DIM  4096
#define M_TOK   (NQ*BATCH)       // 2048
#define M_MEM   (SEQ_S*BATCH)    // 32768

// ---------------------------------------------------------------------------
// Scratch
// ---------------------------------------------------------------------------
#define OFF_X      0LL
#define OFF_QKV    (OFF_X    + 2097152LL)
#define OFF_PACK   (OFF_QKV  + 6291456LL)
#define OFF_SCORES (OFF_PACK + 6291456LL)
#define OFF_O      (OFF_SCORES + 8388608LL)
#define OFF_OREP   (OFF_O    + 2097152LL)
#define OFF_Q1     (OFF_OREP + 2097152LL)
#define OFF_QC     (OFF_Q1   + 2097152LL)
#define OFF_K      (OFF_QC   + 2097152LL)
#define OFF_V      (OFF_K    + 33554432LL)
#define OFF_Q2     (OFF_V    + 33554432LL)
#define OFF_H      (OFF_Q2   + 2097152LL)
#define OFF_QM     (OFF_H    + 8388608LL)
#define OFF_WCVT   (OFF_QM   + 2097152LL)   // rounded weights (tf32), 20971520
#define OFF_MEMR   (OFF_WCVT + 20971520LL)  // rounded memory, 33554432
#define SCRATCH_TOTAL (OFF_MEMR + 33554432LL)

__device__ float g_scratch[SCRATCH_TOTAL];

// weight sub-offsets inside WCVT (floats)
#define W_SAIN   0LL
#define W_SAOUT  3145728LL
#define W_Q      4194304LL
#define W_K      5242880LL
#define W_V      6291456LL
#define W_O      7340032LL
#define W_1      8388608LL
#define W_2      12582912LL
#define W_MASK   16777216LL

// ---------------------------------------------------------------------------
// Helpers
// ---------------------------------------------------------------------------
__device__ __forceinline__ float gelu_exact(float x) {
    return 0.5f * x * (1.0f + erff(x * 0.70710678118654752f));
}
__device__ __forceinline__ float f2tf_f(float x) {
    unsigned u;
    asm("cvt.rna.tf32.f32 %0, %1;" : "=r"(u) : "f"(x));
    return __uint_as_float(u);
}

// ---------------------------------------------------------------------------
// tf32 tensor-core batched GEMM, 4-stage cp.async pipeline.
// 128 threads, 4 warps, warp tile 64x64, CTA tile 128x128x16.
//   C = act( alpha * A @ op(B) + bias + resid )
//   A row-major [M,K]. BLAYOUT 0: B is [N,K] (A@B^T). BLAYOUT 1: B is [K,N].
//   RND: round output to tf32. permP/permQ: output row remap.
// Dynamic smem: 4 stages * (2560 + 2560) floats = 81920 B.
// ---------------------------------------------------------------------------
#define GSTAGES 4
#define GSMEM_BYTES (GSTAGES * 2560 * 2 * 4)

template<int BLAYOUT, int ACT, int RND>
__global__ void __launch_bounds__(128, 2)
gemm_tc(const float* __restrict__ A, const float* __restrict__ B,
        const float* __restrict__ bias, const float* __restrict__ resid,
        float* __restrict__ C,
        int M, int N, int K, int lda, int ldb,
        long long bA, long long bB, long long bC,
        float alpha, int permP, int permQ)
{
    extern __shared__ float smemf[];
    float* As = smemf;                      // [GSTAGES][128][20]
    float* Bs = smemf + GSTAGES * 2560;     // [GSTAGES][128][20] or [16][136]

    const int z  = blockIdx.z;
    const float* Ab = A + (long long)z * bA;
    const float* Bb = B + (long long)z * bB;
    const int m0 = blockIdx.y * 128;
    const int n0 = blockIdx.x * 128;

    const int tid  = threadIdx.x;
    const int lane = tid & 31;
    const int warp = tid >> 5;              // 0..3
    const int warpM = warp >> 1;            // 0..1
    const int warpN = warp & 1;             // 0..1
    const int lr = lane >> 2;               // 0..7
    const int lc = lane & 3;                // 0..3

    // ---- loader indices (128 threads, 4 x 16B chunks per array per stage) --
    const int a_r0 = tid >> 2;              // 0..31 (+32*i)
    const int a_kq = (tid & 3) * 4;         // 0,4,8,12
    const float* Aptr = Ab + (long long)(m0 + a_r0) * lda + a_kq;

    const float* Bptr;
    int b1_k0 = 0, b1_nq = 0;
    if (BLAYOUT == 0) {
        Bptr = Bb + (long long)(n0 + a_r0) * ldb + a_kq;
    } else {
        b1_k0 = tid >> 5;                   // 0..3 (+4*i)
        b1_nq = (tid & 31) * 4;             // 0..124
        Bptr = Bb + (long long)b1_k0 * ldb + n0 + b1_nq;
    }

    const unsigned sAu = (unsigned)__cvta_generic_to_shared(As);
    const unsigned sBu = (unsigned)__cvta_generic_to_shared(Bs);
    const unsigned dA0 = sAu + (unsigned)(a_r0 * 20 + a_kq) * 4u;
    const unsigned dB0 = (BLAYOUT == 0)
        ? sBu + (unsigned)(a_r0 * 20 + a_kq) * 4u
        : sBu + (unsigned)(b1_k0 * 136 + b1_nq) * 4u;

    const int nkt = K >> 4;

    auto issue = [&](int kt, int slot) {
        const long long ka = (long long)kt * 16;
        const unsigned so = (unsigned)slot * 2560u * 4u;
        #pragma unroll
        for (int i = 0; i < 4; i++) {
            const float* g = Aptr + (long long)i * 32 * lda + ka;
            unsigned d = dA0 + so + (unsigned)(i * 32 * 20) * 4u;
            asm volatile("cp.async.cg.shared.global [%0], [%1], 16;\n" :: "r"(d), "l"(g));
        }
        if (BLAYOUT == 0) {
            #pragma unroll
            for (int i = 0; i < 4; i++) {
                const float* g = Bptr + (long long)i * 32 * ldb + ka;
                unsigned d = dB0 + so + (unsigned)(i * 32 * 20) * 4u;
                asm volatile("cp.async.cg.shared.global [%0], [%1], 16;\n" :: "r"(d), "l"(g));
            }
        } else {
            #pragma unroll
            for (int i = 0; i < 4; i++) {
                const float* g = Bptr + (ka + (long long)i * 4) * ldb;
                unsigned d = dB0 + so + (unsigned)(i * 4 * 136) * 4u;
                asm volatile("cp.async.cg.shared.global [%0], [%1], 16;\n" :: "r"(d), "l"(g));
            }
        }
        asm volatile("cp.async.commit_group;\n");
    };

    float acc[4][8][4];
    #pragma unroll
    for (int a = 0; a < 4; a++)
        #pragma unroll
        for (int b = 0; b < 8; b++)
            #pragma unroll
            for (int c = 0; c < 4; c++) acc[a][b][c] = 0.f;

    #pragma unroll
    for (int s = 0; s < GSTAGES - 1; s++) {
        if (s < nkt) issue(s, s);
        else asm volatile("cp.async.commit_group;\n");
    }

    for (int kt = 0; kt < nkt; kt++) {
        asm volatile("cp.async.wait_group %0;\n" :: "n"(GSTAGES - 2));
        __syncthreads();

        const int nx = kt + GSTAGES - 1;
        if (nx < nkt) issue(nx, nx & (GSTAGES - 1));
        else asm volatile("cp.async.commit_group;\n");

        const float* Asb = As + (kt & (GSTAGES - 1)) * 2560;
        const float* Bsb = Bs + (kt & (GSTAGES - 1)) * 2560;

        #pragma unroll
        for (int k8 = 0; k8 < 2; k8++) {
            const int c = k8 * 8 + lc;
            // hoist all 8 B fragments (reused by 4 m-tiles)
            unsigned bf[8][2];
            #pragma unroll
            for (int nt = 0; nt < 8; nt++) {
                if (BLAYOUT == 0) {
                    const int nn = warpN*64 + nt*8 + lr;
                    bf[nt][0] = __float_as_uint(Bsb[nn*20 + c]);
                    bf[nt][1] = __float_as_uint(Bsb[nn*20 + c + 4]);
                } else {
                    const int kk = k8*8 + lc;
                    const int nn = warpN*64 + nt*8 + lr;
                    bf[nt][0] = __float_as_uint(Bsb[kk*136 + nn]);
                    bf[nt][1] = __float_as_uint(Bsb[(kk+4)*136 + nn]);
                }
            }
            #pragma unroll
            for (int mt = 0; mt < 4; mt++) {
                const int r = warpM*64 + mt*16 + lr;
                unsigned a0 = __float_as_uint(Asb[r*20 + c]);
                unsigned a1 = __float_as_uint(Asb[(r+8)*20 + c]);
                unsigned a2 = __float_as_uint(Asb[r*20 + c + 4]);
                unsigned a3 = __float_as_uint(Asb[(r+8)*20 + c + 4]);
                #pragma unroll
                for (int nt = 0; nt < 8; nt++) {
                    asm volatile(
                        "mma.sync.aligned.m16n8k8.row.col.f32.tf32.tf32.f32 "
                        "{%0,%1,%2,%3}, {%4,%5,%6,%7}, {%8,%9}, {%0,%1,%2,%3};"
                        : "+f"(acc[mt][nt][0]), "+f"(acc[mt][nt][1]),
                          "+f"(acc[mt][nt][2]), "+f"(acc[mt][nt][3])
                        : "r"(a0), "r"(a1), "r"(a2), "r"(a3),
                          "r"(bf[nt][0]), "r"(bf[nt][1]));
                }
            }
        }
    }

    // ---- epilogue ----
    #pragma unroll
    for (int mt = 0; mt < 4; mt++) {
        #pragma unroll
        for (int h = 0; h < 2; h++) {
            const int gm = m0 + warpM*64 + mt*16 + lr + h*8;
            const int rm = (permP > 0) ? ((gm % permP) * permQ + gm / permP) : gm;
            const long long base = (long long)z * bC + (long long)rm * N;
            #pragma unroll
            for (int nt = 0; nt < 8; nt++) {
                const int gn = n0 + warpN*64 + nt*8 + 2*lc;
                float v0 = acc[mt][nt][2*h+0] * alpha;
                float v1 = acc[mt][nt][2*h+1] * alpha;
                if (bias)  { v0 += bias[gn]; v1 += bias[gn+1]; }
                if (resid) { v0 += resid[base + gn]; v1 += resid[base + gn + 1]; }
                if (ACT == 1) { v0 = gelu_exact(v0); v1 = gelu_exact(v1); }
                else if (ACT == 2) {
                    v0 = 1.0f / (1.0f + expf(-v0));
                    v1 = 1.0f / (1.0f + expf(-v1));
                }
                if (RND) { v0 = f2tf_f(v0); v1 = f2tf_f(v1); }
                float2 o; o.x = v0; o.y = v1;
                *(float2*)(&C[base + gn]) = o;
            }
        }
    }
}

// ---------------------------------------------------------------------------
// tf32 rounding pass (float4)
// ---------------------------------------------------------------------------
__global__ void round4_k(const float* __restrict__ in, float* __restrict__ out, int n4)
{
    const int i = blockIdx.x * 256 + threadIdx.x;
    if (i < n4) {
        float4 v = ((const float4*)in)[i];
        v.x = f2tf_f(v.x); v.y = f2tf_f(v.y);
        v.z = f2tf_f(v.z); v.w = f2tf_f(v.w);
        ((float4*)out)[i] = v;
    }
}

// ---------------------------------------------------------------------------
// LayerNorm over D=1024 (output tf32-rounded)
// ---------------------------------------------------------------------------
__global__ void ln_k(const float* __restrict__ x, const float* __restrict__ g,
                     const float* __restrict__ b, float* __restrict__ y)
{
    const long long row = blockIdx.x;
    const float* xr = x + row * D_MODEL;
    float* yr = y + row * D_MODEL;
    const int t = threadIdx.x;

    float v[4], s = 0.f, s2 = 0.f;
    #pragma unroll
    for (int i = 0; i < 4; i++) {
        v[i] = xr[t + i * 256];
        s  += v[i];
        s2 += v[i] * v[i];
    }
    #pragma unroll
    for (int o = 16; o > 0; o >>= 1) {
        s  += __shfl_xor_sync(0xFFFFFFFFu, s,  o);
        s2 += __shfl_xor_sync(0xFFFFFFFFu, s2, o);
    }
    __shared__ float shs[8], shs2[8];
    if ((t & 31) == 0) { shs[t >> 5] = s; shs2[t >> 5] = s2; }
    __syncthreads();
    float S = 0.f, S2 = 0.f;
    #pragma unroll
    for (int w = 0; w < 8; w++) { S += shs[w]; S2 += shs2[w]; }

    const float mean = S * (1.0f / D_MODEL);
    const float var  = S2 * (1.0f / D_MODEL) - mean * mean;
    const float inv  = rsqrtf(var + 1e-5f);
    #pragma unroll
    for (int i = 0; i < 4; i++) {
        const int c = t + i * 256;
        yr[c] = f2tf_f((v[i] - mean) * inv * g[c] + b[c]);
    }
}

// ---------------------------------------------------------------------------
// Row softmax (optionally + log(prev_mask + 1e-6)); output tf32-rounded
// ---------------------------------------------------------------------------
__global__ void softmax_k(float* __restrict__ s, const float* __restrict__ pm, int cols)
{
    const long long row = blockIdx.x;
    float* r = s + row * cols;
    const float* pmr = pm ? pm + row * cols : nullptr;
    const int t = threadIdx.x;
    const int nc = cols >> 8;

    float lv[16];
    float mx = -1e30f;
    for (int i = 0; i < nc; i++) {
        float v = r[t + (i << 8)];
        if (pmr) v += logf(pmr[t + (i << 8)] + 1e-6f);
        lv[i] = v;
        mx = fmaxf(mx, v);
    }
    #pragma unroll
    for (int o = 16; o > 0; o >>= 1)
        mx = fmaxf(mx, __shfl_xor_sync(0xFFFFFFFFu, mx, o));
    __shared__ float shm[8], shsum[8];
    if ((t & 31) == 0) shm[t >> 5] = mx;
    __syncthreads();
    float MX = shm[0];
    #pragma unroll
    for (int w = 1; w < 8; w++) MX = fmaxf(MX, shm[w]);

    float sum = 0.f;
    for (int i = 0; i < nc; i++) {
        const float e = expf(lv[i] - MX);
        lv[i] = e;
        sum += e;
    }
    #pragma unroll
    for (int o = 16; o > 0; o >>= 1)
        sum += __shfl_xor_sync(0xFFFFFFFFu, sum, o);
    if ((t & 31) == 0) shsum[t >> 5] = sum;
    __syncthreads();
    float SUM = 0.f;
    #pragma unroll
    for (int w = 0; w < 8; w++) SUM += shsum[w];

    const float inv = 1.0f / SUM;
    for (int i = 0; i < nc; i++) r[t + (i << 8)] = f2tf_f(lv[i] * inv);
}

// ---------------------------------------------------------------------------
// Repack kernels
// ---------------------------------------------------------------------------
__global__ void repack_qkv_k(const float* __restrict__ qkv, float* __restrict__ pack)
{
    const long long gid = (long long)blockIdx.x * 256 + threadIdx.x;
    const int d   = gid & 127;
    const int l   = (gid >> 7) & 255;
    const int bh  = (gid >> 15) & 63;
    const int sec = (int)(gid >> 21);
    const int b = bh >> 3, h = bh & 7;
    const long long in = (long long)(l * BATCH + b) * (3 * D_MODEL)
                         + sec * D_MODEL + h * HDIM + d;
    pack[gid] = f2tf_f(qkv[in]);
}

__global__ void repack_o_k(const float* __restrict__ o, float* __restrict__ out)
{
    const long long gid = (long long)blockIdx.x * 256 + threadIdx.x;
    const int c = gid & 1023;
    const int m = (int)(gid >> 10);
    const int l = m >> 3, b = m & 7;
    const int h = c >> 7, d = c & 127;
    out[gid] = f2tf_f(o[((long long)(b * 8 + h) * 256 + l) * 128 + d]);
}

__global__ void repack_qmask_k(const float* __restrict__ q, float* __restrict__ out)
{
    const long long gid = (long long)blockIdx.x * 256 + threadIdx.x;
    const int d = gid & 1023;
    const int m = (int)(gid >> 10);
    const int b = m >> 8, qq = m & 255;
    out[gid] = f2tf_f(q[(long long)(qq * 8 + b) * 1024 + d]);
}

// ---------------------------------------------------------------------------
// kernel_launch
// ---------------------------------------------------------------------------
extern "C" void kernel_launch(void* const* d_in, const int* in_sizes, int n_in,
                              void* d_out, int out_size)
{
    const float* query    = (const float*)d_in[0];
    const float* memory   = (const float*)d_in[1];
    const float* prevmask = (const float*)d_in[2];
    const float* sa_in_w  = (const float*)d_in[5];
    const float* sa_in_b  = (const float*)d_in[6];
    const float* sa_out_w = (const float*)d_in[7];
    const float* sa_out_b = (const float*)d_in[8];
    const float* ln1_g = (const float*)d_in[9];
    const float* ln1_b = (const float*)d_in[10];
    const float* ln2_g = (const float*)d_in[11];
    const float* ln2_b = (const float*)d_in[12];
    const float* ln3_g = (const float*)d_in[13];
    const float* ln3_b = (const float*)d_in[14];
    const float* wq = (const float*)d_in[15];
    const float* bq = (const float*)d_in[16];
    const float* wk = (const float*)d_in[17];
    const float* bk = (const float*)d_in[18];
    const float* wv = (const float*)d_in[19];
    const float* bv = (const float*)d_in[20];
    const float* wo = (const float*)d_in[21];
    const float* bo = (const float*)d_in[22];
    const float* w1 = (const float*)d_in[23];
    const float* b1 = (const float*)d_in[24];
    const float* w2 = (const float*)d_in[25];
    const float* b2 = (const float*)d_in[26];
    const float* mask_w = (const float*)d_in[27];
    const float* mask_b = (const float*)d_in[28];

    float* scr = nullptr;
    cudaGetSymbolAddress((void**)&scr, g_scratch);

    float* gx    = scr + OFF_X;
    float* gqkv  = scr + OFF_QKV;
    float* gq    = scr + OFF_PACK;
    float* gk    = scr + OFF_PACK + 2097152LL;
    float* gv    = scr + OFF_PACK + 4194304LL;
    float* gsc   = scr + OFF_SCORES;
    float* go    = scr + OFF_O;
    float* gorep = scr + OFF_OREP;
    float* gq1   = scr + OFF_Q1;
    float* gQc   = scr + OFF_QC;
    float* gK    = scr + OFF_K;
    float* gV    = scr + OFF_V;
    float* gq2   = scr + OFF_Q2;
    float* gh    = scr + OFF_H;
    float* gqm   = scr + OFF_QM;
    float* wc    = scr + OFF_WCVT;
    float* memr  = scr + OFF_MEMR;

    float* c_sa_in_w  = wc + W_SAIN;
    float* c_sa_out_w = wc + W_SAOUT;
    float* c_wq = wc + W_Q;
    float* c_wk = wc + W_K;
    float* c_wv = wc + W_V;
    float* c_wo = wc + W_O;
    float* c_w1 = wc + W_1;
    float* c_w2 = wc + W_2;
    float* c_mask_w = wc + W_MASK;

    float* out_q = (float*)d_out;
    float* out_m = out_q + (long long)M_TOK * D_MODEL;

    const float inv_sqrt_hd = 0.088388347648318447f;
    const float inv_sqrt_d  = 0.03125f;

    cudaFuncSetAttribute(gemm_tc<0,0,0>, cudaFuncAttributeMaxDynamicSharedMemorySize, GSMEM_BYTES);
    cudaFuncSetAttribute(gemm_tc<1,0,0>, cudaFuncAttributeMaxDynamicSharedMemorySize, GSMEM_BYTES);
    cudaFuncSetAttribute(gemm_tc<0,0,1>, cudaFuncAttributeMaxDynamicSharedMemorySize, GSMEM_BYTES);
    cudaFuncSetAttribute(gemm_tc<1,0,1>, cudaFuncAttributeMaxDynamicSharedMemorySize, GSMEM_BYTES);
    cudaFuncSetAttribute(gemm_tc<0,1,1>, cudaFuncAttributeMaxDynamicSharedMemorySize, GSMEM_BYTES);
    cudaFuncSetAttribute(gemm_tc<0,2,0>, cudaFuncAttributeMaxDynamicSharedMemorySize, GSMEM_BYTES);

    // --- 0. tf32 pre-round weights + memory ---
    round4_k<<<3072, 256>>>(sa_in_w, c_sa_in_w, 786432);
    round4_k<<<1024, 256>>>(sa_out_w, c_sa_out_w, 262144);
    round4_k<<<1024, 256>>>(wq, c_wq, 262144);
    round4_k<<<1024, 256>>>(wk, c_wk, 262144);
    round4_k<<<1024, 256>>>(wv, c_wv, 262144);
    round4_k<<<1024, 256>>>(wo, c_wo, 262144);
    round4_k<<<4096, 256>>>(w1, c_w1, 1048576);
    round4_k<<<4096, 256>>>(w2, c_w2, 1048576);
    round4_k<<<4096, 256>>>(mask_w, c_mask_w, 1048576);
    round4_k<<<32768, 256>>>(memory, memr, 8388608);

    // 1. ln1(query)
    ln_k<<<M_TOK, 256>>>(query, ln1_g, ln1_b, gx);

    // 2. QKV projection
    gemm_tc<0,0,0><<<dim3(24,16,1), 128, GSMEM_BYTES>>>(gx, c_sa_in_w, sa_in_b, nullptr, gqkv,
        M_TOK, 3*D_MODEL, D_MODEL, D_MODEL, D_MODEL, 0, 0, 0, 1.0f, 0, 0);

    // 3. pack q,k,v
    repack_qkv_k<<<24576, 256>>>(gqkv, gq);

    // 4. self-attn scores (batched 64)
    gemm_tc<0,0,0><<<dim3(2,2,64), 128, GSMEM_BYTES>>>(gq, gk, nullptr, nullptr, gsc,
        NQ, NQ, HDIM, HDIM, HDIM, 256LL*128, 256LL*128, 256LL*256,
        inv_sqrt_hd, 0, 0);

    // 5. softmax
    softmax_k<<<64*256, 256>>>(gsc, nullptr, 256);

    // 6. o = attn @ v
    gemm_tc<1,0,0><<<dim3(1,2,64), 128, GSMEM_BYTES>>>(gsc, gv, nullptr, nullptr, go,
        NQ, HDIM, NQ, NQ, HDIM, 256LL*256, 256LL*128, 256LL*128, 1.0f, 0, 0);

    // 7. repack o
    repack_o_k<<<8192, 256>>>(go, gorep);

    // 8. self out-proj + residual
    gemm_tc<0,0,0><<<dim3(8,16,1), 128, GSMEM_BYTES>>>(gorep, c_sa_out_w, sa_out_b, query, gq1,
        M_TOK, D_MODEL, D_MODEL, D_MODEL, D_MODEL, 0, 0, 0, 1.0f, 0, 0);

    // 9. ln2
    ln_k<<<M_TOK, 256>>>(gq1, ln2_g, ln2_b, gx);

    // 10. Q proj -> [B,NQ,D]
    gemm_tc<0,0,1><<<dim3(8,16,1), 128, GSMEM_BYTES>>>(gx, c_wq, bq, nullptr, gQc,
        M_TOK, D_MODEL, D_MODEL, D_MODEL, D_MODEL, 0, 0, 0, 1.0f, 8, 256);

    // 11/12. K,V proj -> [B,S,D]
    gemm_tc<0,0,1><<<dim3(8,256,1), 128, GSMEM_BYTES>>>(memr, c_wk, bk, nullptr, gK,
        M_MEM, D_MODEL, D_MODEL, D_MODEL, D_MODEL, 0, 0, 0, 1.0f, 8, 4096);
    gemm_tc<0,0,1><<<dim3(8,256,1), 128, GSMEM_BYTES>>>(memr, c_wv, bv, nullptr, gV,
        M_MEM, D_MODEL, D_MODEL, D_MODEL, D_MODEL, 0, 0, 0, 1.0f, 8, 4096);

    // 13. cross scores
    gemm_tc<0,0,0><<<dim3(32,2,8), 128, GSMEM_BYTES>>>(gQc, gK, nullptr, nullptr, gsc,
        NQ, SEQ_S, D_MODEL, D_MODEL, D_MODEL,
        256LL*1024, 4096LL*1024, 256LL*4096, inv_sqrt_d, 0, 0);

    // 14. softmax + log(prev_mask)
    softmax_k<<<BATCH*NQ, 256>>>(gsc, prevmask, SEQ_S);

    // 15. attn_out = attn @ V
    gemm_tc<1,0,1><<<dim3(8,2,8), 128, GSMEM_BYTES>>>(gsc, gV, nullptr, nullptr, go,
        NQ, D_MODEL, SEQ_S, SEQ_S, D_MODEL,
        256LL*4096, 4096LL*1024, 256LL*1024, 1.0f, 0, 0);

    // 16. cross out-proj + residual -> [NQ,B,D]
    gemm_tc<0,0,0><<<dim3(8,16,1), 128, GSMEM_BYTES>>>(go, c_wo, bo, gq1, gq2,
        M_TOK, D_MODEL, D_MODEL, D_MODEL, D_MODEL, 0, 0, 0, 1.0f, 256, 8);

    // 17. ln3
    ln_k<<<M_TOK, 256>>>(gq2, ln3_g, ln3_b, gx);

    // 18. FFN1 + GELU
    gemm_tc<0,1,1><<<dim3(32,16,1), 128, GSMEM_BYTES>>>(gx, c_w1, b1, nullptr, gh,
        M_TOK, FF_DIM, D_MODEL, D_MODEL, D_MODEL, 0, 0, 0, 1.0f, 0, 0);

    // 19. FFN2 + residual -> final query
    gemm_tc<0,0,0><<<dim3(8,16,1), 128, GSMEM_BYTES>>>(gh, c_w2, b2, gq2, out_q,
        M_TOK, D_MODEL, FF_DIM, FF_DIM, FF_DIM, 0, 0, 0, 1.0f, 0, 0);

    // 20. gather final query to [B,NQ,D]
    repack_qmask_k<<<8192, 256>>>(out_q, gqm);

    // 21. mask logits + sigmoid
    gemm_tc<0,2,0><<<dim3(32,16,1), 128, GSMEM_BYTES>>>(gqm, c_mask_w, mask_b, nullptr, out_m,
        M_TOK, SEQ_S, D_MODEL, D_MODEL, D_MODEL, 0, 0, 0, 1.0f, 0, 0);
}